// round 5
// baseline (speedup 1.0000x reference)
#include <cuda_runtime.h>
#include <math.h>

#define NROWS 16384
#define ZDIM  100
#define EDIM  400
#define MOD0  4000
#define MOD1  2000

// Scratch for topic matrices (beta @ alpha^T), stored row-major (Z, M).
__device__ __align__(16) float g_topic0[ZDIM * MOD0];
__device__ __align__(16) float g_topic1[ZDIM * MOD1];

__device__ __forceinline__ unsigned long long fma2(unsigned long long a,
                                                   unsigned long long b,
                                                   unsigned long long c) {
    unsigned long long d;
    asm("fma.rn.f32x2 %0, %1, %2, %3;" : "=l"(d) : "l"(a), "l"(b), "l"(c));
    return d;
}
__device__ __forceinline__ float f2lo(unsigned long long v) {
    return __uint_as_float((unsigned)v);
}
__device__ __forceinline__ float f2hi(unsigned long long v) {
    return __uint_as_float((unsigned)(v >> 32));
}

// ---------------------------------------------------------------------------
// Kernel A: topic = beta @ alpha^T    (Z=100 x M), alpha (M, E), beta (Z, E)
// CTA: 128 columns (strided per-lane: m = mbase + tcol + 32k), all 100 z.
// ---------------------------------------------------------------------------
template <int M>
__global__ void topic_kernel(const float* __restrict__ alpha,
                             const float* __restrict__ beta) {
    constexpr int EC = 50;           // E chunk
    __shared__ float a_s[128][EC + 1];   // alpha tile, padded (conflict-free)
    __shared__ float b_s[104][EC + 1];   // beta tile, z padded to 104

    float* topic = (M == MOD0) ? g_topic0 : g_topic1;

    const int tid  = threadIdx.x;
    const int tcol = tid & 31;
    const int trow = tid >> 5;           // 0..7
    const int mbase = blockIdx.x * 128;

    float acc[13][4];
#pragma unroll
    for (int j = 0; j < 13; j++)
#pragma unroll
        for (int k = 0; k < 4; k++) acc[j][k] = 0.f;

    for (int eb = 0; eb < EDIM; eb += EC) {
        for (int i = tid; i < 128 * EC; i += 256) {
            int mm = i / EC, e = i % EC;
            int gm = mbase + mm;
            a_s[mm][e] = (gm < M) ? alpha[(size_t)gm * EDIM + eb + e] : 0.f;
        }
        for (int i = tid; i < 104 * EC; i += 256) {
            int zz = i / EC, e = i % EC;
            b_s[zz][e] = (zz < ZDIM) ? beta[(size_t)zz * EDIM + eb + e] : 0.f;
        }
        __syncthreads();
#pragma unroll 2
        for (int e = 0; e < EC; e++) {
            float av[4];
#pragma unroll
            for (int k = 0; k < 4; k++) av[k] = a_s[tcol + 32 * k][e];
#pragma unroll
            for (int j = 0; j < 13; j++) {
                float bv = b_s[trow + 8 * j][e];
#pragma unroll
                for (int k = 0; k < 4; k++) acc[j][k] += bv * av[k];
            }
        }
        __syncthreads();
    }

#pragma unroll
    for (int j = 0; j < 13; j++) {
        int z = trow + 8 * j;
        if (z < ZDIM) {
#pragma unroll
            for (int k = 0; k < 4; k++) {
                int m = mbase + tcol + 32 * k;
                if (m < M) topic[(size_t)z * M + m] = acc[j][k];
            }
        }
    }
}

// ---------------------------------------------------------------------------
// Kernel B: logits = theta @ topic + bias[dom] ; out = logits - logsumexp(row)
// CTA: 32 rows x full M. 256 threads: trow = tid/32 -> 4 rows, tcol -> 4 cols
// per 128-col tile. Each warp owns one 4-row group: warp shuffles do the
// row-wise reductions. Phase 1 stores raw logits + online (max,sumexp);
// phase 2 re-reads (L2-hot) and subtracts lse.
// ---------------------------------------------------------------------------
template <int M>
__global__ void __launch_bounds__(256)
main_kernel(const float* __restrict__ theta,
            const float* __restrict__ bias,
            const int*   __restrict__ dom,
            float*       __restrict__ out) {
    constexpr int R = 32;
    constexpr int NTILES = (M + 127) / 128;

    __shared__ unsigned long long th_s[R * ZDIM];  // theta duplicated in f32x2
    __shared__ int d_s[R];

    const float* topic = (M == MOD0) ? g_topic0 : g_topic1;

    const int tid  = threadIdx.x;
    const int tcol = tid & 31;
    const int trow = tid >> 5;
    const int rowbase = blockIdx.x * R;
    const int r0 = trow * 4;

    for (int i = tid; i < R * ZDIM; i += 256) {
        unsigned u = __float_as_uint(theta[(size_t)rowbase * ZDIM + i]);
        th_s[i] = ((unsigned long long)u << 32) | (unsigned long long)u;
    }
    if (tid < R) d_s[tid] = dom[rowbase + tid];
    __syncthreads();

    float rm[4], rs[4], lse[4];
#pragma unroll
    for (int i = 0; i < 4; i++) { rm[i] = -1e30f; rs[i] = 0.f; }

    for (int tile = 0; tile < NTILES; tile++) {
        const int c = tile * 128 + tcol * 4;
        const bool valid = (c < M);
        const float* topicC = topic + (valid ? c : 0);

        unsigned long long a01[4], a23[4];
#pragma unroll
        for (int i = 0; i < 4; i++) { a01[i] = 0ull; a23[i] = 0ull; }

#pragma unroll 10
        for (int z = 0; z < ZDIM; z++) {
            ulonglong2 tv =
                *reinterpret_cast<const ulonglong2*>(topicC + (size_t)z * M);
#pragma unroll
            for (int i = 0; i < 4; i++) {
                unsigned long long a2 = th_s[(r0 + i) * ZDIM + z];
                a01[i] = fma2(a2, tv.x, a01[i]);
                a23[i] = fma2(a2, tv.y, a23[i]);
            }
        }

#pragma unroll
        for (int i = 0; i < 4; i++) {
            float l0, l1, l2, l3;
            l0 = f2lo(a01[i]); l1 = f2hi(a01[i]);
            l2 = f2lo(a23[i]); l3 = f2hi(a23[i]);
            if (valid) {
                int d = d_s[r0 + i];
                float4 bv = *reinterpret_cast<const float4*>(
                    bias + (size_t)d * M + c);
                l0 += bv.x; l1 += bv.y; l2 += bv.z; l3 += bv.w;
                float4 st = make_float4(l0, l1, l2, l3);
                *reinterpret_cast<float4*>(
                    out + (size_t)(rowbase + r0 + i) * M + c) = st;
            } else {
                l0 = l1 = l2 = l3 = -1e30f;
            }
            float tm = fmaxf(fmaxf(l0, l1), fmaxf(l2, l3));
#pragma unroll
            for (int off = 16; off; off >>= 1)
                tm = fmaxf(tm, __shfl_xor_sync(0xffffffffu, tm, off));
            float ts = __expf(l0 - tm) + __expf(l1 - tm) +
                       __expf(l2 - tm) + __expf(l3 - tm);
#pragma unroll
            for (int off = 16; off; off >>= 1)
                ts += __shfl_xor_sync(0xffffffffu, ts, off);
            float nm = fmaxf(rm[i], tm);
            rs[i] = rs[i] * __expf(rm[i] - nm) + ts * __expf(tm - nm);
            rm[i] = nm;
        }
    }

#pragma unroll
    for (int i = 0; i < 4; i++) lse[i] = rm[i] + logf(rs[i]);

    // Phase 2: subtract lse (re-read just-written logits; L2-hot).
    for (int tile = 0; tile < NTILES; tile++) {
        const int c = tile * 128 + tcol * 4;
        if (c < M) {
#pragma unroll
            for (int i = 0; i < 4; i++) {
                float4* p = reinterpret_cast<float4*>(
                    out + (size_t)(rowbase + r0 + i) * M + c);
                float4 v = *p;
                v.x -= lse[i]; v.y -= lse[i]; v.z -= lse[i]; v.w -= lse[i];
                *p = v;
            }
        }
    }
}

extern "C" void kernel_launch(void* const* d_in, const int* in_sizes, int n_in,
                              void* d_out, int out_size) {
    const float* theta  = (const float*)d_in[0];
    const float* alpha0 = (const float*)d_in[1];
    const float* alpha1 = (const float*)d_in[2];
    const float* beta   = (const float*)d_in[3];
    const float* bias0  = (const float*)d_in[4];
    const float* bias1  = (const float*)d_in[5];
    const int*   dom    = (const int*)d_in[6];

    float* out0 = (float*)d_out;
    float* out1 = out0 + (size_t)NROWS * MOD0;

    topic_kernel<MOD0><<<(MOD0 + 127) / 128, 256>>>(alpha0, beta);
    topic_kernel<MOD1><<<(MOD1 + 127) / 128, 256>>>(alpha1, beta);

    main_kernel<MOD0><<<NROWS / 32, 256>>>(theta, bias0, dom, out0);
    main_kernel<MOD1><<<NROWS / 32, 256>>>(theta, bias1, dom, out1);
}